// round 1
// baseline (speedup 1.0000x reference)
#include <cuda_runtime.h>
#include <cstdint>

#define N_MAX 100000
#define CIN   64
#define CMID  64
#define COUT  128
#define BN_EPS 1e-5

// ---------------- device scratch (static: no allocations allowed) ----------------
__device__ int    g_count[N_MAX];
__device__ float  g_T1[(size_t)N_MAX * CMID];    // feat @ W1 + b1          (25.6 MB)
__device__ float  g_T2[(size_t)N_MAX * COUT];    // relu(bn1) @ W2 + b2     (51.2 MB)
__device__ double g_sum1[CMID], g_sq1[CMID];
__device__ double g_sum2[COUT], g_sq2[COUT];
__device__ float  g_s1[CMID], g_t1[CMID];
__device__ float  g_s2[COUT], g_t2[COUT];
__device__ int    g_is64;

// ---------------- K0: zero counters + accumulators ----------------
__global__ void k_zero(int n) {
    int i  = blockIdx.x * blockDim.x + threadIdx.x;
    int st = gridDim.x * blockDim.x;
    for (int j = i; j < n; j += st) g_count[j] = 0;
    if (i < CMID) { g_sum1[i] = 0.0; g_sq1[i] = 0.0; }
    if (i < COUT) { g_sum2[i] = 0.0; g_sq2[i] = 0.0; }
}

// ---------------- K1a: detect idx dtype (int32 vs int64) ----------------
// idx values are in [0, n) (n = 100000 < 2^31). If the buffer is int64
// little-endian, every odd 32-bit word is 0. For int32 data those words are
// random indices; 64 of them all being zero has probability ~1e-320.
__global__ void k_detect(const int* w, int nk) {
    __shared__ int ok;
    if (threadIdx.x == 0) ok = 1;
    __syncthreads();
    int m = 64;
    if (nk < 128) m = nk / 2;
    if ((int)threadIdx.x < m) {
        if (w[2 * threadIdx.x + 1] != 0) ok = 0;  // benign race: only writes 0
    }
    __syncthreads();
    if (threadIdx.x == 0) g_is64 = ok;
}

// ---------------- K1b: histogram of idx ----------------
__global__ void k_hist(const void* idxp, int nk) {
    int is64 = g_is64;
    int i  = blockIdx.x * blockDim.x + threadIdx.x;
    int st = gridDim.x * blockDim.x;
    if (is64) {
        const long long* p = (const long long*)idxp;
        for (int e = i; e < nk; e += st) atomicAdd(&g_count[(int)p[e]], 1);
    } else {
        const int* p = (const int*)idxp;
        for (int e = i; e < nk; e += st) atomicAdd(&g_count[p[e]], 1);
    }
}

// ---------------- K2: T1 = feat @ W1 + b1   (n x 64 @ 64 x 64) ----------------
// 256 threads = 16(col-groups) x 16(row-groups); 4x4 micro-tile; 64 rows/block.
__global__ __launch_bounds__(256) void k_gemm1(const float* __restrict__ feat,
                                               const float* __restrict__ W1,
                                               const float* __restrict__ b1, int n) {
    __shared__ float As[64 * 65];   // As[k*65 + r]  (transposed feat tile, pad 65)
    __shared__ float Bs[64 * 64];   // Bs[k*64 + c]  (natural W1 layout)
    __shared__ float bs[64];

    int tid = threadIdx.x;
    int tx = tid & 15;        // col group: cols tx*4 .. tx*4+3
    int ty = tid >> 4;        // row group: rows ty*4 .. ty*4+3
    int row0 = blockIdx.x * 64;

    for (int t = tid; t < 64 * 64; t += 256) Bs[t] = W1[t];
    if (tid < 64) bs[tid] = b1[tid];
    for (int t = tid; t < 64 * 64; t += 256) {
        int r = t >> 6, k = t & 63;
        int gr = row0 + r;
        As[k * 65 + r] = (gr < n) ? feat[(size_t)gr * CIN + k] : 0.0f;
    }
    __syncthreads();

    float acc[4][4];
#pragma unroll
    for (int i = 0; i < 4; i++)
#pragma unroll
        for (int j = 0; j < 4; j++) acc[i][j] = 0.0f;

#pragma unroll 4
    for (int k = 0; k < 64; k++) {
        float a[4];
#pragma unroll
        for (int i = 0; i < 4; i++) a[i] = As[k * 65 + ty * 4 + i];
        float4 bv = *(const float4*)&Bs[k * 64 + tx * 4];
#pragma unroll
        for (int i = 0; i < 4; i++) {
            acc[i][0] = fmaf(a[i], bv.x, acc[i][0]);
            acc[i][1] = fmaf(a[i], bv.y, acc[i][1]);
            acc[i][2] = fmaf(a[i], bv.z, acc[i][2]);
            acc[i][3] = fmaf(a[i], bv.w, acc[i][3]);
        }
    }

    float4 bias = *(const float4*)&bs[tx * 4];
#pragma unroll
    for (int i = 0; i < 4; i++) {
        int gr = row0 + ty * 4 + i;
        if (gr < n) {
            float4 o;
            o.x = acc[i][0] + bias.x; o.y = acc[i][1] + bias.y;
            o.z = acc[i][2] + bias.z; o.w = acc[i][3] + bias.w;
            *(float4*)&g_T1[(size_t)gr * CMID + tx * 4] = o;
        }
    }
}

// ---------------- K3/K5: count-weighted channel stats over a table ----------------
template <int C>
__global__ __launch_bounds__(256) void k_stats(int n) {
    const float* T = (C == CMID) ? g_T1 : g_T2;
    double* dS = (C == CMID) ? g_sum1 : g_sum2;
    double* dQ = (C == CMID) ? g_sq1  : g_sq2;

    const int RL = 256 / C;                 // rows in flight per block
    int tid = threadIdx.x;
    int c  = tid % C;
    int ty = tid / C;

    double s = 0.0, q = 0.0;
    for (int r = blockIdx.x * RL + ty; r < n; r += gridDim.x * RL) {
        double w = (double)g_count[r];
        double v = (double)T[(size_t)r * C + c];
        s += w * v;
        q += w * v * v;
    }
    __shared__ double shs[256], shq[256];
    shs[tid] = s; shq[tid] = q;
    __syncthreads();
    if (ty == 0) {
#pragma unroll
        for (int u = 1; u < RL; u++) { s += shs[c + u * C]; q += shq[c + u * C]; }
        atomicAdd(&dS[c], s);
        atomicAdd(&dQ[c], q);
    }
}

// ---------------- finalize BN affine: s = g*rsqrt(var+eps), t = be - mean*s ----------------
template <int C>
__global__ void k_fin(const float* __restrict__ g, const float* __restrict__ be, double M) {
    int c = threadIdx.x;
    if (c >= C) return;
    const double* S = (C == CMID) ? g_sum1 : g_sum2;
    const double* Q = (C == CMID) ? g_sq1  : g_sq2;
    float* so = (C == CMID) ? g_s1 : g_s2;
    float* to = (C == CMID) ? g_t1 : g_t2;
    double mean = S[c] / M;
    double var  = Q[c] / M - mean * mean;
    double rs   = 1.0 / sqrt(var + BN_EPS);
    float  sc   = (float)((double)g[c] * rs);
    so[c] = sc;
    to[c] = (float)((double)be[c] - mean * (double)sc);
}

// ---------------- K4: T2 = relu(s1*T1+t1) @ W2 + b2  (n x 64 @ 64 x 128) ----------------
// 256 threads = 32(col-groups) x 8(row-groups); 4x4 micro-tile; 32 rows/block.
__global__ __launch_bounds__(256) void k_gemm2(const float* __restrict__ W2,
                                               const float* __restrict__ b2, int n) {
    __shared__ float As[64 * 33];    // As[k*33 + r], r < 32 (h1 tile, transposed)
    __shared__ float Bs[64 * 128];   // W2 natural layout (32 KB)
    __shared__ float b2s[128];

    int tid = threadIdx.x;
    int tx = tid & 31;        // cols tx*4 .. tx*4+3 (128 total)
    int ty = tid >> 5;        // rows ty*4 .. ty*4+3 (32 total)
    int row0 = blockIdx.x * 32;

    for (int t = tid; t < 64 * 128; t += 256) Bs[t] = W2[t];
    if (tid < 128) b2s[tid] = b2[tid];
    for (int t = tid; t < 32 * 64; t += 256) {
        int r = t >> 6, k = t & 63;
        int gr = row0 + r;
        float v = (gr < n) ? g_T1[(size_t)gr * CMID + k] : 0.0f;
        float h = fmaf(g_s1[k], v, g_t1[k]);
        As[k * 33 + r] = fmaxf(h, 0.0f);
    }
    __syncthreads();

    float acc[4][4];
#pragma unroll
    for (int i = 0; i < 4; i++)
#pragma unroll
        for (int j = 0; j < 4; j++) acc[i][j] = 0.0f;

#pragma unroll 4
    for (int k = 0; k < 64; k++) {
        float a[4];
#pragma unroll
        for (int i = 0; i < 4; i++) a[i] = As[k * 33 + ty * 4 + i];
        float4 bv = *(const float4*)&Bs[k * 128 + tx * 4];
#pragma unroll
        for (int i = 0; i < 4; i++) {
            acc[i][0] = fmaf(a[i], bv.x, acc[i][0]);
            acc[i][1] = fmaf(a[i], bv.y, acc[i][1]);
            acc[i][2] = fmaf(a[i], bv.z, acc[i][2]);
            acc[i][3] = fmaf(a[i], bv.w, acc[i][3]);
        }
    }

    float4 bias = *(const float4*)&b2s[tx * 4];
#pragma unroll
    for (int i = 0; i < 4; i++) {
        int gr = row0 + ty * 4 + i;
        if (gr < n) {
            float4 o;
            o.x = acc[i][0] + bias.x; o.y = acc[i][1] + bias.y;
            o.z = acc[i][2] + bias.z; o.w = acc[i][3] + bias.w;
            *(float4*)&g_T2[(size_t)gr * COUT + tx * 4] = o;
        }
    }
}

// ---------------- K6: gather + bn2-affine + relu + max over k neighbors ----------------
// One warp per output point. Lane l owns channels 4l..4l+3 (float4).
__global__ __launch_bounds__(256) void k_gather(const void* __restrict__ idxp,
                                                float* __restrict__ out, int n, int k) {
    int warp = (blockIdx.x * blockDim.x + threadIdx.x) >> 5;
    int lane = threadIdx.x & 31;
    if (warp >= n) return;
    int is64 = g_is64;

    int r_mine = 0;
    if (lane < k) {
        if (is64) r_mine = (int)((const long long*)idxp)[(size_t)warp * k + lane];
        else      r_mine = ((const int*)idxp)[(size_t)warp * k + lane];
    }

    float4 s2 = *(const float4*)&g_s2[lane * 4];
    float4 t2 = *(const float4*)&g_t2[lane * 4];
    float4 m = make_float4(0.0f, 0.0f, 0.0f, 0.0f);   // relu => max starts at 0

    for (int j = 0; j < k; j++) {
        int r = __shfl_sync(0xffffffffu, r_mine, j);
        float4 v = *(const float4*)&g_T2[(size_t)r * COUT + lane * 4];
        m.x = fmaxf(m.x, fmaf(s2.x, v.x, t2.x));
        m.y = fmaxf(m.y, fmaf(s2.y, v.y, t2.y));
        m.z = fmaxf(m.z, fmaf(s2.z, v.z, t2.z));
        m.w = fmaxf(m.w, fmaf(s2.w, v.w, t2.w));
    }
    *(float4*)&out[(size_t)warp * COUT + lane * 4] = m;
}

// ---------------- host launcher ----------------
extern "C" void kernel_launch(void* const* d_in, const int* in_sizes, int n_in,
                              void* d_out, int out_size) {
    const float* feat = (const float*)d_in[0];
    const void*  idx  = d_in[1];
    const float* W1   = (const float*)d_in[2];
    const float* b1   = (const float*)d_in[3];
    const float* g1   = (const float*)d_in[4];
    const float* be1  = (const float*)d_in[5];
    const float* W2   = (const float*)d_in[6];
    const float* b2   = (const float*)d_in[7];
    const float* g2   = (const float*)d_in[8];
    const float* be2  = (const float*)d_in[9];
    float* out = (float*)d_out;

    int n  = in_sizes[0] / CIN;      // 100000
    int nk = in_sizes[1];            // n * k (element count)
    int k  = nk / n;                 // 16
    double M = (double)nk;

    k_zero<<<(n + 255) / 256, 256>>>(n);
    k_detect<<<1, 64>>>((const int*)idx, nk);
    k_hist<<<1024, 256>>>(idx, nk);

    k_gemm1<<<(n + 63) / 64, 256>>>(feat, W1, b1, n);
    k_stats<CMID><<<592, 256>>>(n);
    k_fin<CMID><<<1, CMID>>>(g1, be1, M);

    k_gemm2<<<(n + 31) / 32, 256>>>(W2, b2, n);
    k_stats<COUT><<<592, 256>>>(n);
    k_fin<COUT><<<1, COUT>>>(g2, be2, M);

    k_gather<<<(n + 7) / 8, 256>>>(idx, out, n, k);
}

// round 2
// speedup vs baseline: 1.8817x; 1.8817x over previous
#include <cuda_runtime.h>
#include <cuda_fp16.h>
#include <cstdint>

#define N_MAX 100000
#define CIN   64
#define CMID  64
#define COUT  128
#define BN_EPS 1e-5
#define NSLOT 16

// ---------------- device scratch (static: no allocations allowed) ----------------
__device__ int    g_count[N_MAX];
__device__ float  g_T1[(size_t)N_MAX * CMID];    // feat @ W1 + b1              (25.6 MB)
__device__ float  g_T2[(size_t)N_MAX * COUT];    // relu(bn1) @ W2 + b2 (pre-BN2, 51.2 MB)
__device__ __half g_T2h[(size_t)N_MAX * COUT];   // relu(bn2(T2)) in fp16       (25.6 MB)
__device__ double g_sum1[NSLOT * CMID], g_sq1[NSLOT * CMID];
__device__ double g_sum2[NSLOT * COUT], g_sq2[NSLOT * COUT];
__device__ float  g_s1[CMID], g_t1[CMID];
__device__ float  g_s2[COUT], g_t2[COUT];
__device__ int    g_is64;

// ---------------- K0: zero counters + accumulators ----------------
__global__ void k_zero(int n) {
    int i  = blockIdx.x * blockDim.x + threadIdx.x;
    int st = gridDim.x * blockDim.x;
    for (int j = i; j < n; j += st) g_count[j] = 0;
    if (i < NSLOT * CMID) { g_sum1[i] = 0.0; g_sq1[i] = 0.0; }
    if (i < NSLOT * COUT) { g_sum2[i] = 0.0; g_sq2[i] = 0.0; }
}

// ---------------- K1a: detect idx dtype (int32 vs int64) ----------------
// idx values are in [0, n), n < 2^31. For little-endian int64 every odd 32-bit
// word is 0; for int32 data, 64 consecutive odd words all being 0 is ~impossible.
__global__ void k_detect(const int* w, int nk) {
    __shared__ int ok;
    if (threadIdx.x == 0) ok = 1;
    __syncthreads();
    int m = 64;
    if (nk < 128) m = nk / 2;
    if ((int)threadIdx.x < m) {
        if (w[2 * threadIdx.x + 1] != 0) ok = 0;  // benign race: only writes 0
    }
    __syncthreads();
    if (threadIdx.x == 0) g_is64 = ok;
}

// ---------------- K1b: histogram of idx ----------------
__global__ void k_hist(const void* idxp, int nk) {
    int is64 = g_is64;
    int i  = blockIdx.x * blockDim.x + threadIdx.x;
    int st = gridDim.x * blockDim.x;
    if (is64) {
        const long long* p = (const long long*)idxp;
        for (int e = i; e < nk; e += st) atomicAdd(&g_count[(int)p[e]], 1);
    } else {
        const int* p = (const int*)idxp;
        for (int e = i; e < nk; e += st) atomicAdd(&g_count[p[e]], 1);
    }
}

// ---------------- K2: T1 = feat @ W1 + b1  (n x 64 @ 64 x 64) + fused BN1 stats ----
// 256 threads = 16(col) x 16(row) groups; 4x4 micro-tile; 64 rows/block.
__global__ __launch_bounds__(256) void k_gemm1(const float* __restrict__ feat,
                                               const float* __restrict__ W1,
                                               const float* __restrict__ b1, int n) {
    __shared__ float As[64 * 65];   // As[k*65 + r]; reused for stats reduction
    __shared__ float Bs[64 * 64];
    __shared__ float bs[64];

    int tid = threadIdx.x;
    int tx = tid & 15;        // cols tx*4 .. tx*4+3
    int ty = tid >> 4;        // rows ty*4 .. ty*4+3
    int row0 = blockIdx.x * 64;

    for (int t = tid; t < 64 * 64; t += 256) Bs[t] = W1[t];
    if (tid < 64) bs[tid] = b1[tid];
    for (int t = tid; t < 64 * 64; t += 256) {
        int r = t >> 6, k = t & 63;
        int gr = row0 + r;
        As[k * 65 + r] = (gr < n) ? feat[(size_t)gr * CIN + k] : 0.0f;
    }
    __syncthreads();

    float acc[4][4];
#pragma unroll
    for (int i = 0; i < 4; i++)
#pragma unroll
        for (int j = 0; j < 4; j++) acc[i][j] = 0.0f;

#pragma unroll 8
    for (int k = 0; k < 64; k++) {
        float a[4];
#pragma unroll
        for (int i = 0; i < 4; i++) a[i] = As[k * 65 + ty * 4 + i];
        float4 bv = *(const float4*)&Bs[k * 64 + tx * 4];
#pragma unroll
        for (int i = 0; i < 4; i++) {
            acc[i][0] = fmaf(a[i], bv.x, acc[i][0]);
            acc[i][1] = fmaf(a[i], bv.y, acc[i][1]);
            acc[i][2] = fmaf(a[i], bv.z, acc[i][2]);
            acc[i][3] = fmaf(a[i], bv.w, acc[i][3]);
        }
    }

    float4 bias = *(const float4*)&bs[tx * 4];
    float sj[4] = {0, 0, 0, 0}, qj[4] = {0, 0, 0, 0};
#pragma unroll
    for (int i = 0; i < 4; i++) {
        int gr = row0 + ty * 4 + i;
        if (gr < n) {
            float4 o;
            o.x = acc[i][0] + bias.x; o.y = acc[i][1] + bias.y;
            o.z = acc[i][2] + bias.z; o.w = acc[i][3] + bias.w;
            *(float4*)&g_T1[(size_t)gr * CMID + tx * 4] = o;
            float w = (float)g_count[gr];
            sj[0] += w * o.x; qj[0] += w * o.x * o.x;
            sj[1] += w * o.y; qj[1] += w * o.y * o.y;
            sj[2] += w * o.z; qj[2] += w * o.z * o.z;
            sj[3] += w * o.w; qj[3] += w * o.w * o.w;
        }
    }

    // block-level stats reduction (reuse As as scratch)
    __syncthreads();
    float* shs = As;            // [16][64]
    float* shq = As + 1024;     // [16][64]
#pragma unroll
    for (int j = 0; j < 4; j++) {
        shs[ty * 64 + tx * 4 + j] = sj[j];
        shq[ty * 64 + tx * 4 + j] = qj[j];
    }
    __syncthreads();
    if (tid < 64) {
        double s = 0.0, q = 0.0;
#pragma unroll
        for (int u = 0; u < 16; u++) { s += (double)shs[u * 64 + tid]; q += (double)shq[u * 64 + tid]; }
        int slot = blockIdx.x & (NSLOT - 1);
        atomicAdd(&g_sum1[slot * CMID + tid], s);
        atomicAdd(&g_sq1[slot * CMID + tid], q);
    }
}

// ---------------- finalize BN affine: s = g*rsqrt(var+eps), t = be - mean*s ------
template <int C>
__global__ void k_fin(const float* __restrict__ g, const float* __restrict__ be, double M) {
    int c = threadIdx.x;
    if (c >= C) return;
    const double* S = (C == CMID) ? g_sum1 : g_sum2;
    const double* Q = (C == CMID) ? g_sq1  : g_sq2;
    float* so = (C == CMID) ? g_s1 : g_s2;
    float* to = (C == CMID) ? g_t1 : g_t2;
    double s = 0.0, q = 0.0;
#pragma unroll
    for (int u = 0; u < NSLOT; u++) { s += S[u * C + c]; q += Q[u * C + c]; }
    double mean = s / M;
    double var  = q / M - mean * mean;
    double rs   = 1.0 / sqrt(var + BN_EPS);
    float  sc   = (float)((double)g[c] * rs);
    so[c] = sc;
    to[c] = (float)((double)be[c] - mean * (double)sc);
}

// ---------------- K4: T2 = relu(bn1(T1)) @ W2 + b2 (n x 64 @ 64 x 128) + BN2 stats
// 256 threads = 32(col) x 8(row) groups; 8x4 micro-tile; 64 rows/block.
// K split into 2 chunks of 32 for Bs to keep static smem < 48KB.
__global__ __launch_bounds__(256) void k_gemm2(const float* __restrict__ W2,
                                               const float* __restrict__ b2, int n) {
    __shared__ float As[64 * 65];    // 16.6 KB; reused for stats reduction
    __shared__ float Bs[32 * 128];   // 16 KB (one K-chunk of W2)
    __shared__ float b2s[128];

    int tid = threadIdx.x;
    int tx = tid & 31;        // cols tx*4 .. tx*4+3 (128 total)
    int ty = tid >> 5;        // rows ty*8 .. ty*8+7 (64 total)
    int row0 = blockIdx.x * 64;

    // fill As with relu(bn1(T1)) — transposed [k][r]
    for (int t = tid; t < 64 * 64; t += 256) {
        int r = t >> 6, kk = t & 63;
        int gr = row0 + r;
        float v = (gr < n) ? g_T1[(size_t)gr * CMID + kk] : 0.0f;
        As[kk * 65 + r] = fmaxf(fmaf(g_s1[kk], v, g_t1[kk]), 0.0f);
    }
    if (tid < 128) b2s[tid] = b2[tid];

    float acc[8][4];
#pragma unroll
    for (int i = 0; i < 8; i++)
#pragma unroll
        for (int j = 0; j < 4; j++) acc[i][j] = 0.0f;

    for (int kc = 0; kc < 2; kc++) {
        __syncthreads();   // first iter: covers As/b2s fill; later: protect Bs reuse
        for (int t = tid; t < 32 * 128; t += 256) Bs[t] = W2[kc * 32 * 128 + t];
        __syncthreads();
#pragma unroll 8
        for (int kk = 0; kk < 32; kk++) {
            int k = kc * 32 + kk;
            float a[8];
#pragma unroll
            for (int i = 0; i < 8; i++) a[i] = As[k * 65 + ty * 8 + i];
            float4 bv = *(const float4*)&Bs[kk * 128 + tx * 4];
#pragma unroll
            for (int i = 0; i < 8; i++) {
                acc[i][0] = fmaf(a[i], bv.x, acc[i][0]);
                acc[i][1] = fmaf(a[i], bv.y, acc[i][1]);
                acc[i][2] = fmaf(a[i], bv.z, acc[i][2]);
                acc[i][3] = fmaf(a[i], bv.w, acc[i][3]);
            }
        }
    }

    float4 bias = *(const float4*)&b2s[tx * 4];
    float sj[4] = {0, 0, 0, 0}, qj[4] = {0, 0, 0, 0};
#pragma unroll
    for (int i = 0; i < 8; i++) {
        int gr = row0 + ty * 8 + i;
        if (gr < n) {
            float4 o;
            o.x = acc[i][0] + bias.x; o.y = acc[i][1] + bias.y;
            o.z = acc[i][2] + bias.z; o.w = acc[i][3] + bias.w;
            *(float4*)&g_T2[(size_t)gr * COUT + tx * 4] = o;
            float w = (float)g_count[gr];
            sj[0] += w * o.x; qj[0] += w * o.x * o.x;
            sj[1] += w * o.y; qj[1] += w * o.y * o.y;
            sj[2] += w * o.z; qj[2] += w * o.z * o.z;
            sj[3] += w * o.w; qj[3] += w * o.w * o.w;
        }
    }

    // block-level stats reduction (reuse As as scratch)
    __syncthreads();
    float* shs = As;            // [8][128]
    float* shq = As + 1024;     // [8][128]
#pragma unroll
    for (int j = 0; j < 4; j++) {
        shs[ty * 128 + tx * 4 + j] = sj[j];
        shq[ty * 128 + tx * 4 + j] = qj[j];
    }
    __syncthreads();
    if (tid < 128) {
        double s = 0.0, q = 0.0;
#pragma unroll
        for (int u = 0; u < 8; u++) { s += (double)shs[u * 128 + tid]; q += (double)shq[u * 128 + tid]; }
        int slot = blockIdx.x & (NSLOT - 1);
        atomicAdd(&g_sum2[slot * COUT + tid], s);
        atomicAdd(&g_sq2[slot * COUT + tid], q);
    }
}

// ---------------- K5: apply BN2 affine + relu, downconvert to fp16 table --------
__global__ __launch_bounds__(256) void k_affine2(int total4) {
    int i = blockIdx.x * blockDim.x + threadIdx.x;
    if (i >= total4) return;
    size_t base = (size_t)i * 4;
    int c = (int)(base & (COUT - 1));
    float4 v = *(const float4*)&g_T2[base];
    float4 s = *(const float4*)&g_s2[c];
    float4 t = *(const float4*)&g_t2[c];
    float h0 = fmaxf(fmaf(s.x, v.x, t.x), 0.0f);
    float h1 = fmaxf(fmaf(s.y, v.y, t.y), 0.0f);
    float h2 = fmaxf(fmaf(s.z, v.z, t.z), 0.0f);
    float h3 = fmaxf(fmaf(s.w, v.w, t.w), 0.0f);
    union { uint2 u; __half2 h[2]; } o;
    o.h[0] = __floats2half2_rn(h0, h1);
    o.h[1] = __floats2half2_rn(h2, h3);
    *(uint2*)&g_T2h[base] = o.u;
}

// ---------------- K6: gather + max over k neighbors (fp16 table) ----------------
// One warp per output point. Lane l owns channels 4l..4l+3 (uint2 = 2 x half2).
__global__ __launch_bounds__(256) void k_gather(const void* __restrict__ idxp,
                                                float* __restrict__ out, int n, int k) {
    int warp = (blockIdx.x * blockDim.x + threadIdx.x) >> 5;
    int lane = threadIdx.x & 31;
    if (warp >= n) return;
    int is64 = g_is64;

    __half2 m0 = __float2half2_rn(0.0f);   // relu => values >= 0
    __half2 m1 = m0;

    if (k == 16) {
        int r_mine = 0;
        if (lane < 16) {
            if (is64) r_mine = (int)((const long long*)idxp)[(size_t)warp * 16 + lane];
            else      r_mine = ((const int*)idxp)[(size_t)warp * 16 + lane];
        }
#pragma unroll
        for (int j = 0; j < 16; j++) {
            int r = __shfl_sync(0xffffffffu, r_mine, j);
            uint2 v = *(const uint2*)&g_T2h[(size_t)r * COUT + lane * 4];
            m0 = __hmax2(m0, *(__half2*)&v.x);
            m1 = __hmax2(m1, *(__half2*)&v.y);
        }
    } else {
        for (int j = 0; j < k; j++) {
            int r;
            if (is64) r = (int)((const long long*)idxp)[(size_t)warp * k + j];
            else      r = ((const int*)idxp)[(size_t)warp * k + j];
            uint2 v = *(const uint2*)&g_T2h[(size_t)r * COUT + lane * 4];
            m0 = __hmax2(m0, *(__half2*)&v.x);
            m1 = __hmax2(m1, *(__half2*)&v.y);
        }
    }

    float2 f0 = __half22float2(m0);
    float2 f1 = __half22float2(m1);
    *(float4*)&out[(size_t)warp * COUT + lane * 4] = make_float4(f0.x, f0.y, f1.x, f1.y);
}

// ---------------- host launcher ----------------
extern "C" void kernel_launch(void* const* d_in, const int* in_sizes, int n_in,
                              void* d_out, int out_size) {
    const float* feat = (const float*)d_in[0];
    const void*  idx  = d_in[1];
    const float* W1   = (const float*)d_in[2];
    const float* b1   = (const float*)d_in[3];
    const float* g1   = (const float*)d_in[4];
    const float* be1  = (const float*)d_in[5];
    const float* W2   = (const float*)d_in[6];
    const float* b2   = (const float*)d_in[7];
    const float* g2   = (const float*)d_in[8];
    const float* be2  = (const float*)d_in[9];
    float* out = (float*)d_out;

    int n  = in_sizes[0] / CIN;      // 100000
    int nk = in_sizes[1];            // n * k
    int k  = nk / n;                 // 16
    double M = (double)nk;

    k_zero<<<(n + 255) / 256, 256>>>(n);
    k_detect<<<1, 64>>>((const int*)idx, nk);
    k_hist<<<1024, 256>>>(idx, nk);

    k_gemm1<<<(n + 63) / 64, 256>>>(feat, W1, b1, n);
    k_fin<CMID><<<1, CMID>>>(g1, be1, M);

    k_gemm2<<<(n + 63) / 64, 256>>>(W2, b2, n);
    k_fin<COUT><<<1, COUT>>>(g2, be2, M);

    int total4 = n * (COUT / 4);
    k_affine2<<<(total4 + 255) / 256, 256>>>(total4);

    k_gather<<<(n + 7) / 8, 256>>>(idx, out, n, k);
}

// round 3
// speedup vs baseline: 1.9092x; 1.0146x over previous
#include <cuda_runtime.h>
#include <cuda_fp16.h>
#include <cstdint>

#define N_MAX 100000
#define CIN   64
#define CMID  64
#define COUT  128
#define BN_EPS 1e-5
#define NSLOT 16

// ---------------- device scratch (static: no allocations allowed) ----------------
__device__ int    g_count[N_MAX];
__device__ float  g_T1[(size_t)N_MAX * CMID];    // feat @ W1 + b1              (25.6 MB)
__device__ float  g_T2[(size_t)N_MAX * COUT];    // relu(bn1) @ W2 + b2 (pre-BN2, 51.2 MB)
__device__ __half g_T2h[(size_t)N_MAX * COUT];   // relu(bn2(T2)) in fp16       (25.6 MB)
__device__ double g_sum1[NSLOT * CMID], g_sq1[NSLOT * CMID];
__device__ double g_sum2[NSLOT * COUT], g_sq2[NSLOT * COUT];
__device__ float  g_s1[CMID], g_t1[CMID];
__device__ float  g_s2[COUT], g_t2[COUT];
__device__ int    g_is64;

// ---------------- K0: zero counters + accumulators ----------------
__global__ void k_zero(int n) {
    int i  = blockIdx.x * blockDim.x + threadIdx.x;
    int st = gridDim.x * blockDim.x;
    for (int j = i; j < n; j += st) g_count[j] = 0;
    if (i < NSLOT * CMID) { g_sum1[i] = 0.0; g_sq1[i] = 0.0; }
    if (i < NSLOT * COUT) { g_sum2[i] = 0.0; g_sq2[i] = 0.0; }
}

// ---------------- K1a: detect idx dtype (int32 vs int64) ----------------
// idx values are in [0, n), n < 2^31. For little-endian int64 every odd 32-bit
// word is 0; for int32 data, 64 consecutive odd words all being 0 is ~impossible.
__global__ void k_detect(const int* w, int nk) {
    __shared__ int ok;
    if (threadIdx.x == 0) ok = 1;
    __syncthreads();
    int m = 64;
    if (nk < 128) m = nk / 2;
    if ((int)threadIdx.x < m) {
        if (w[2 * threadIdx.x + 1] != 0) ok = 0;  // benign race: only writes 0
    }
    __syncthreads();
    if (threadIdx.x == 0) g_is64 = ok;
}

// ---------------- K1b: histogram of idx ----------------
__global__ void k_hist(const void* idxp, int nk) {
    int is64 = g_is64;
    int i  = blockIdx.x * blockDim.x + threadIdx.x;
    int st = gridDim.x * blockDim.x;
    if (is64) {
        const long long* p = (const long long*)idxp;
        for (int e = i; e < nk; e += st) atomicAdd(&g_count[(int)p[e]], 1);
    } else {
        const int* p = (const int*)idxp;
        for (int e = i; e < nk; e += st) atomicAdd(&g_count[p[e]], 1);
    }
}

// ---------------- K2: T1 = feat @ W1 + b1  (n x 64 @ 64 x 64) + fused BN1 stats ----
// 256 threads = 16(col) x 16(row) groups; 4x4 micro-tile; 64 rows/block.
__global__ __launch_bounds__(256) void k_gemm1(const float* __restrict__ feat,
                                               const float* __restrict__ W1,
                                               const float* __restrict__ b1, int n) {
    __shared__ float As[64 * 65];   // As[k*65 + r]; reused for stats reduction
    __shared__ float Bs[64 * 64];
    __shared__ float bs[64];

    int tid = threadIdx.x;
    int tx = tid & 15;        // cols tx*4 .. tx*4+3
    int ty = tid >> 4;        // rows ty*4 .. ty*4+3
    int row0 = blockIdx.x * 64;

    for (int t = tid; t < 64 * 64; t += 256) Bs[t] = W1[t];
    if (tid < 64) bs[tid] = b1[tid];
    for (int t = tid; t < 64 * 64; t += 256) {
        int r = t >> 6, k = t & 63;
        int gr = row0 + r;
        As[k * 65 + r] = (gr < n) ? feat[(size_t)gr * CIN + k] : 0.0f;
    }
    __syncthreads();

    float acc[4][4];
#pragma unroll
    for (int i = 0; i < 4; i++)
#pragma unroll
        for (int j = 0; j < 4; j++) acc[i][j] = 0.0f;

#pragma unroll 8
    for (int k = 0; k < 64; k++) {
        float a[4];
#pragma unroll
        for (int i = 0; i < 4; i++) a[i] = As[k * 65 + ty * 4 + i];
        float4 bv = *(const float4*)&Bs[k * 64 + tx * 4];
#pragma unroll
        for (int i = 0; i < 4; i++) {
            acc[i][0] = fmaf(a[i], bv.x, acc[i][0]);
            acc[i][1] = fmaf(a[i], bv.y, acc[i][1]);
            acc[i][2] = fmaf(a[i], bv.z, acc[i][2]);
            acc[i][3] = fmaf(a[i], bv.w, acc[i][3]);
        }
    }

    float4 bias = *(const float4*)&bs[tx * 4];
    float sj[4] = {0, 0, 0, 0}, qj[4] = {0, 0, 0, 0};
#pragma unroll
    for (int i = 0; i < 4; i++) {
        int gr = row0 + ty * 4 + i;
        if (gr < n) {
            float4 o;
            o.x = acc[i][0] + bias.x; o.y = acc[i][1] + bias.y;
            o.z = acc[i][2] + bias.z; o.w = acc[i][3] + bias.w;
            *(float4*)&g_T1[(size_t)gr * CMID + tx * 4] = o;
            float w = (float)g_count[gr];
            sj[0] += w * o.x; qj[0] += w * o.x * o.x;
            sj[1] += w * o.y; qj[1] += w * o.y * o.y;
            sj[2] += w * o.z; qj[2] += w * o.z * o.z;
            sj[3] += w * o.w; qj[3] += w * o.w * o.w;
        }
    }

    // block-level stats reduction (reuse As as scratch)
    __syncthreads();
    float* shs = As;            // [16][64]
    float* shq = As + 1024;     // [16][64]
#pragma unroll
    for (int j = 0; j < 4; j++) {
        shs[ty * 64 + tx * 4 + j] = sj[j];
        shq[ty * 64 + tx * 4 + j] = qj[j];
    }
    __syncthreads();
    if (tid < 64) {
        double s = 0.0, q = 0.0;
#pragma unroll
        for (int u = 0; u < 16; u++) { s += (double)shs[u * 64 + tid]; q += (double)shq[u * 64 + tid]; }
        int slot = blockIdx.x & (NSLOT - 1);
        atomicAdd(&g_sum1[slot * CMID + tid], s);
        atomicAdd(&g_sq1[slot * CMID + tid], q);
    }
}

// ---------------- finalize BN affine: s = g*rsqrt(var+eps), t = be - mean*s ------
template <int C>
__global__ void k_fin(const float* __restrict__ g, const float* __restrict__ be, double M) {
    int c = threadIdx.x;
    if (c >= C) return;
    const double* S = (C == CMID) ? g_sum1 : g_sum2;
    const double* Q = (C == CMID) ? g_sq1  : g_sq2;
    float* so = (C == CMID) ? g_s1 : g_s2;
    float* to = (C == CMID) ? g_t1 : g_t2;
    double s = 0.0, q = 0.0;
#pragma unroll
    for (int u = 0; u < NSLOT; u++) { s += S[u * C + c]; q += Q[u * C + c]; }
    double mean = s / M;
    double var  = q / M - mean * mean;
    double rs   = 1.0 / sqrt(var + BN_EPS);
    float  sc   = (float)((double)g[c] * rs);
    so[c] = sc;
    to[c] = (float)((double)be[c] - mean * (double)sc);
}

// ---------------- K4: T2 = relu(bn1(T1)) @ W2 + b2 (n x 64 @ 64 x 128) + BN2 stats
// 256 threads = 32(col) x 8(row) groups; 8x4 micro-tile; 64 rows/block.
// K split into 2 chunks of 32 for Bs to keep static smem < 48KB.
__global__ __launch_bounds__(256) void k_gemm2(const float* __restrict__ W2,
                                               const float* __restrict__ b2, int n) {
    __shared__ float As[64 * 65];    // 16.6 KB; reused for stats reduction
    __shared__ float Bs[32 * 128];   // 16 KB (one K-chunk of W2)
    __shared__ float b2s[128];

    int tid = threadIdx.x;
    int tx = tid & 31;        // cols tx*4 .. tx*4+3 (128 total)
    int ty = tid >> 5;        // rows ty*8 .. ty*8+7 (64 total)
    int row0 = blockIdx.x * 64;

    // fill As with relu(bn1(T1)) — transposed [k][r]
    for (int t = tid; t < 64 * 64; t += 256) {
        int r = t >> 6, kk = t & 63;
        int gr = row0 + r;
        float v = (gr < n) ? g_T1[(size_t)gr * CMID + kk] : 0.0f;
        As[kk * 65 + r] = fmaxf(fmaf(g_s1[kk], v, g_t1[kk]), 0.0f);
    }
    if (tid < 128) b2s[tid] = b2[tid];

    float acc[8][4];
#pragma unroll
    for (int i = 0; i < 8; i++)
#pragma unroll
        for (int j = 0; j < 4; j++) acc[i][j] = 0.0f;

    for (int kc = 0; kc < 2; kc++) {
        __syncthreads();   // first iter: covers As/b2s fill; later: protect Bs reuse
        for (int t = tid; t < 32 * 128; t += 256) Bs[t] = W2[kc * 32 * 128 + t];
        __syncthreads();
#pragma unroll 8
        for (int kk = 0; kk < 32; kk++) {
            int k = kc * 32 + kk;
            float a[8];
#pragma unroll
            for (int i = 0; i < 8; i++) a[i] = As[k * 65 + ty * 8 + i];
            float4 bv = *(const float4*)&Bs[kk * 128 + tx * 4];
#pragma unroll
            for (int i = 0; i < 8; i++) {
                acc[i][0] = fmaf(a[i], bv.x, acc[i][0]);
                acc[i][1] = fmaf(a[i], bv.y, acc[i][1]);
                acc[i][2] = fmaf(a[i], bv.z, acc[i][2]);
                acc[i][3] = fmaf(a[i], bv.w, acc[i][3]);
            }
        }
    }

    float4 bias = *(const float4*)&b2s[tx * 4];
    float sj[4] = {0, 0, 0, 0}, qj[4] = {0, 0, 0, 0};
#pragma unroll
    for (int i = 0; i < 8; i++) {
        int gr = row0 + ty * 8 + i;
        if (gr < n) {
            float4 o;
            o.x = acc[i][0] + bias.x; o.y = acc[i][1] + bias.y;
            o.z = acc[i][2] + bias.z; o.w = acc[i][3] + bias.w;
            *(float4*)&g_T2[(size_t)gr * COUT + tx * 4] = o;
            float w = (float)g_count[gr];
            sj[0] += w * o.x; qj[0] += w * o.x * o.x;
            sj[1] += w * o.y; qj[1] += w * o.y * o.y;
            sj[2] += w * o.z; qj[2] += w * o.z * o.z;
            sj[3] += w * o.w; qj[3] += w * o.w * o.w;
        }
    }

    // block-level stats reduction (reuse As as scratch)
    __syncthreads();
    float* shs = As;            // [8][128]
    float* shq = As + 1024;     // [8][128]
#pragma unroll
    for (int j = 0; j < 4; j++) {
        shs[ty * 128 + tx * 4 + j] = sj[j];
        shq[ty * 128 + tx * 4 + j] = qj[j];
    }
    __syncthreads();
    if (tid < 128) {
        double s = 0.0, q = 0.0;
#pragma unroll
        for (int u = 0; u < 8; u++) { s += (double)shs[u * 128 + tid]; q += (double)shq[u * 128 + tid]; }
        int slot = blockIdx.x & (NSLOT - 1);
        atomicAdd(&g_sum2[slot * COUT + tid], s);
        atomicAdd(&g_sq2[slot * COUT + tid], q);
    }
}

// ---------------- K5: apply BN2 affine + relu, downconvert to fp16 table --------
__global__ __launch_bounds__(256) void k_affine2(int total4) {
    int i = blockIdx.x * blockDim.x + threadIdx.x;
    if (i >= total4) return;
    size_t base = (size_t)i * 4;
    int c = (int)(base & (COUT - 1));
    float4 v = *(const float4*)&g_T2[base];
    float4 s = *(const float4*)&g_s2[c];
    float4 t = *(const float4*)&g_t2[c];
    float h0 = fmaxf(fmaf(s.x, v.x, t.x), 0.0f);
    float h1 = fmaxf(fmaf(s.y, v.y, t.y), 0.0f);
    float h2 = fmaxf(fmaf(s.z, v.z, t.z), 0.0f);
    float h3 = fmaxf(fmaf(s.w, v.w, t.w), 0.0f);
    union { uint2 u; __half2 h[2]; } o;
    o.h[0] = __floats2half2_rn(h0, h1);
    o.h[1] = __floats2half2_rn(h2, h3);
    *(uint2*)&g_T2h[base] = o.u;
}

// ---------------- K6: gather + max over k neighbors (fp16 table) ----------------
// One warp per output point. Lane l owns channels 4l..4l+3 (uint2 = 2 x half2).
__global__ __launch_bounds__(256) void k_gather(const void* __restrict__ idxp,
                                                float* __restrict__ out, int n, int k) {
    int warp = (blockIdx.x * blockDim.x + threadIdx.x) >> 5;
    int lane = threadIdx.x & 31;
    if (warp >= n) return;
    int is64 = g_is64;

    __half2 m0 = __float2half2_rn(0.0f);   // relu => values >= 0
    __half2 m1 = m0;

    if (k == 16) {
        int r_mine = 0;
        if (lane < 16) {
            if (is64) r_mine = (int)((const long long*)idxp)[(size_t)warp * 16 + lane];
            else      r_mine = ((const int*)idxp)[(size_t)warp * 16 + lane];
        }
#pragma unroll
        for (int j = 0; j < 16; j++) {
            int r = __shfl_sync(0xffffffffu, r_mine, j);
            uint2 v = *(const uint2*)&g_T2h[(size_t)r * COUT + lane * 4];
            m0 = __hmax2(m0, *(__half2*)&v.x);
            m1 = __hmax2(m1, *(__half2*)&v.y);
        }
    } else {
        for (int j = 0; j < k; j++) {
            int r;
            if (is64) r = (int)((const long long*)idxp)[(size_t)warp * k + j];
            else      r = ((const int*)idxp)[(size_t)warp * k + j];
            uint2 v = *(const uint2*)&g_T2h[(size_t)r * COUT + lane * 4];
            m0 = __hmax2(m0, *(__half2*)&v.x);
            m1 = __hmax2(m1, *(__half2*)&v.y);
        }
    }

    float2 f0 = __half22float2(m0);
    float2 f1 = __half22float2(m1);
    *(float4*)&out[(size_t)warp * COUT + lane * 4] = make_float4(f0.x, f0.y, f1.x, f1.y);
}

// ---------------- host launcher ----------------
extern "C" void kernel_launch(void* const* d_in, const int* in_sizes, int n_in,
                              void* d_out, int out_size) {
    const float* feat = (const float*)d_in[0];
    const void*  idx  = d_in[1];
    const float* W1   = (const float*)d_in[2];
    const float* b1   = (const float*)d_in[3];
    const float* g1   = (const float*)d_in[4];
    const float* be1  = (const float*)d_in[5];
    const float* W2   = (const float*)d_in[6];
    const float* b2   = (const float*)d_in[7];
    const float* g2   = (const float*)d_in[8];
    const float* be2  = (const float*)d_in[9];
    float* out = (float*)d_out;

    int n  = in_sizes[0] / CIN;      // 100000
    int nk = in_sizes[1];            // n * k
    int k  = nk / n;                 // 16
    double M = (double)nk;

    k_zero<<<(n + 255) / 256, 256>>>(n);
    k_detect<<<1, 64>>>((const int*)idx, nk);
    k_hist<<<1024, 256>>>(idx, nk);

    k_gemm1<<<(n + 63) / 64, 256>>>(feat, W1, b1, n);
    k_fin<CMID><<<1, CMID>>>(g1, be1, M);

    k_gemm2<<<(n + 63) / 64, 256>>>(W2, b2, n);
    k_fin<COUT><<<1, COUT>>>(g2, be2, M);

    int total4 = n * (COUT / 4);
    k_affine2<<<(total4 + 255) / 256, 256>>>(total4);

    k_gather<<<(n + 7) / 8, 256>>>(idx, out, n, k);
}

// round 4
// speedup vs baseline: 2.1834x; 1.1436x over previous
#include <cuda_runtime.h>
#include <cuda_fp16.h>
#include <cstdint>

#define N_MAX 100000
#define CIN   64
#define CMID  64
#define COUT  128
#define BN_EPS 1e-5
#define NSLOT 16

// ---------------- device scratch (static: no allocations allowed) ----------------
__device__ int    g_count[N_MAX];
__device__ float  g_T1[(size_t)N_MAX * CMID];    // feat @ W1 + b1 (25.6 MB)
__device__ __half g_T2h[(size_t)N_MAX * COUT];   // T2 pre-BN2, fp16 (25.6 MB)
__device__ double g_sum1[NSLOT * CMID], g_sq1[NSLOT * CMID];
__device__ double g_sum2[NSLOT * COUT], g_sq2[NSLOT * COUT];
__device__ float  g_s1[CMID], g_t1[CMID];
__device__ float  g_s2[COUT], g_t2[COUT];
__device__ int    g_is64;

// ---------------- K0: zero counters + accumulators ----------------
__global__ void k_zero(int n) {
    int i  = blockIdx.x * blockDim.x + threadIdx.x;
    int st = gridDim.x * blockDim.x;
    for (int j = i; j < n; j += st) g_count[j] = 0;
    if (i < NSLOT * CMID) { g_sum1[i] = 0.0; g_sq1[i] = 0.0; }
    if (i < NSLOT * COUT) { g_sum2[i] = 0.0; g_sq2[i] = 0.0; }
}

// ---------------- K1a: detect idx dtype (int32 vs int64) ----------------
// idx in [0, n), n < 2^31. Little-endian int64 => every odd 32-bit word is 0.
__global__ void k_detect(const int* w, int nk) {
    __shared__ int ok;
    if (threadIdx.x == 0) ok = 1;
    __syncthreads();
    int m = 64;
    if (nk < 128) m = nk / 2;
    if ((int)threadIdx.x < m) {
        if (w[2 * threadIdx.x + 1] != 0) ok = 0;  // benign race: only writes 0
    }
    __syncthreads();
    if (threadIdx.x == 0) g_is64 = ok;
}

// ---------------- K1b: histogram of idx (vectorized int4 loads) ----------------
__global__ void k_hist(const void* idxp, int nk) {
    int is64 = g_is64;
    int i  = blockIdx.x * blockDim.x + threadIdx.x;
    int st = gridDim.x * blockDim.x;
    if ((nk & 3) == 0) {
        const int4* p = (const int4*)idxp;
        int nq = nk >> 2;          // int4 chunks of the underlying int32 stream
        if (is64) {
            nq = nk >> 1;          // int64: int4 = 2 entries {x=lo0, z=lo1}
            for (int e = i; e < nq; e += st) {
                int4 v = p[e];
                atomicAdd(&g_count[v.x], 1);
                atomicAdd(&g_count[v.z], 1);
            }
        } else {
            for (int e = i; e < nq; e += st) {
                int4 v = p[e];
                atomicAdd(&g_count[v.x], 1);
                atomicAdd(&g_count[v.y], 1);
                atomicAdd(&g_count[v.z], 1);
                atomicAdd(&g_count[v.w], 1);
            }
        }
    } else {
        if (is64) {
            const long long* p = (const long long*)idxp;
            for (int e = i; e < nk; e += st) atomicAdd(&g_count[(int)p[e]], 1);
        } else {
            const int* p = (const int*)idxp;
            for (int e = i; e < nk; e += st) atomicAdd(&g_count[p[e]], 1);
        }
    }
}

// ---------------- K2: T1 = feat @ W1 + b1 (128 rows/block, 8x4 tiles) + BN1 stats
static const int SMEM1 = (64 * 129 + 64 * 64 + 64) * 4;   // As + W1 + bias = 49.9KB
__global__ __launch_bounds__(256) void k_gemm1(const float* __restrict__ feat,
                                               const float* __restrict__ W1,
                                               const float* __restrict__ b1, int n) {
    extern __shared__ float sm[];
    float* As = sm;                 // As[k*129 + r], r < 128
    float* Bs = sm + 64 * 129;      // W1 natural [k][c]
    float* bs = Bs + 64 * 64;

    int tid = threadIdx.x;
    int tx = tid & 15;        // cols tx*4 .. tx*4+3  (64)
    int ty = tid >> 4;        // rows ty*8 .. ty*8+7  (128)
    int row0 = blockIdx.x * 128;

    for (int t = tid; t < 64 * 64; t += 256) Bs[t] = W1[t];
    if (tid < 64) bs[tid] = b1[tid];
    // feat tile: float4 loads, transpose into As
    for (int t = tid; t < 128 * 16; t += 256) {
        int r = t >> 4, q = t & 15;
        int gr = row0 + r;
        float4 v = (gr < n) ? ((const float4*)feat)[(size_t)gr * 16 + q]
                            : make_float4(0.f, 0.f, 0.f, 0.f);
        As[(4 * q + 0) * 129 + r] = v.x;
        As[(4 * q + 1) * 129 + r] = v.y;
        As[(4 * q + 2) * 129 + r] = v.z;
        As[(4 * q + 3) * 129 + r] = v.w;
    }
    __syncthreads();

    float acc[8][4];
#pragma unroll
    for (int i = 0; i < 8; i++)
#pragma unroll
        for (int j = 0; j < 4; j++) acc[i][j] = 0.0f;

#pragma unroll 4
    for (int k = 0; k < 64; k++) {
        float a[8];
#pragma unroll
        for (int i = 0; i < 8; i++) a[i] = As[k * 129 + ty * 8 + i];
        float4 bv = *(const float4*)&Bs[k * 64 + tx * 4];
#pragma unroll
        for (int i = 0; i < 8; i++) {
            acc[i][0] = fmaf(a[i], bv.x, acc[i][0]);
            acc[i][1] = fmaf(a[i], bv.y, acc[i][1]);
            acc[i][2] = fmaf(a[i], bv.z, acc[i][2]);
            acc[i][3] = fmaf(a[i], bv.w, acc[i][3]);
        }
    }

    float4 bias = *(const float4*)&bs[tx * 4];
    float sj[4] = {0, 0, 0, 0}, qj[4] = {0, 0, 0, 0};
#pragma unroll
    for (int i = 0; i < 8; i++) {
        int gr = row0 + ty * 8 + i;
        if (gr < n) {
            float4 o;
            o.x = acc[i][0] + bias.x; o.y = acc[i][1] + bias.y;
            o.z = acc[i][2] + bias.z; o.w = acc[i][3] + bias.w;
            *(float4*)&g_T1[(size_t)gr * CMID + tx * 4] = o;
            float w = (float)g_count[gr];
            sj[0] += w * o.x; qj[0] += w * o.x * o.x;
            sj[1] += w * o.y; qj[1] += w * o.y * o.y;
            sj[2] += w * o.z; qj[2] += w * o.z * o.z;
            sj[3] += w * o.w; qj[3] += w * o.w * o.w;
        }
    }

    // block-level stats reduction (reuse As as scratch: 2 x 16 x 64 floats)
    __syncthreads();
    float* shs = As;
    float* shq = As + 1024;
#pragma unroll
    for (int j = 0; j < 4; j++) {
        shs[ty * 64 + tx * 4 + j] = sj[j];
        shq[ty * 64 + tx * 4 + j] = qj[j];
    }
    __syncthreads();
    if (tid < 64) {
        double s = 0.0, q = 0.0;
#pragma unroll
        for (int u = 0; u < 16; u++) { s += (double)shs[u * 64 + tid]; q += (double)shq[u * 64 + tid]; }
        int slot = blockIdx.x & (NSLOT - 1);
        atomicAdd(&g_sum1[slot * CMID + tid], s);
        atomicAdd(&g_sq1[slot * CMID + tid], q);
    }
}

// ---------------- finalize BN affine: s = g*rsqrt(var+eps), t = be - mean*s ------
template <int C>
__global__ void k_fin(const float* __restrict__ g, const float* __restrict__ be, double M) {
    int c = threadIdx.x;
    if (c >= C) return;
    const double* S = (C == CMID) ? g_sum1 : g_sum2;
    const double* Q = (C == CMID) ? g_sq1  : g_sq2;
    float* so = (C == CMID) ? g_s1 : g_s2;
    float* to = (C == CMID) ? g_t1 : g_t2;
    double s = 0.0, q = 0.0;
#pragma unroll
    for (int u = 0; u < NSLOT; u++) { s += S[u * C + c]; q += Q[u * C + c]; }
    double mean = s / M;
    double var  = q / M - mean * mean;
    double rs   = 1.0 / sqrt(var + BN_EPS);
    float  sc   = (float)((double)g[c] * rs);
    so[c] = sc;
    to[c] = (float)((double)be[c] - mean * (double)sc);
}

// ---------------- K4: T2 = relu(bn1(T1)) @ W2 + b2 (128 rows/block, 16x4 tiles)
// + BN2 stats from f32 regs + fp16 (pre-BN2) store.
static const int SMEM2 = (64 * 129 + 32 * 128 + 128) * 4;  // As + W2chunk + bias = 50.0KB
__global__ __launch_bounds__(256) void k_gemm2(const float* __restrict__ W2,
                                               const float* __restrict__ b2, int n) {
    extern __shared__ float sm[];
    float* As  = sm;                 // As[k*129 + r], r < 128  (h1 transposed)
    float* Bs  = sm + 64 * 129;      // one 32-row K-chunk of W2 [kk][c]
    float* b2s = Bs + 32 * 128;

    int tid = threadIdx.x;
    int tx = tid & 31;        // cols tx*4 .. tx*4+3   (128)
    int ty = tid >> 5;        // rows ty*16 .. ty*16+15 (128); uniform per warp
    int row0 = blockIdx.x * 128;

    // fill As with relu(bn1(T1)) — transposed [k][r]
    for (int t = tid; t < 128 * 64; t += 256) {
        int r = t >> 6, kk = t & 63;
        int gr = row0 + r;
        float v = (gr < n) ? g_T1[(size_t)gr * CMID + kk] : 0.0f;
        As[kk * 129 + r] = fmaxf(fmaf(g_s1[kk], v, g_t1[kk]), 0.0f);
    }
    if (tid < 128) b2s[tid] = b2[tid];

    float acc[16][4];
#pragma unroll
    for (int i = 0; i < 16; i++)
#pragma unroll
        for (int j = 0; j < 4; j++) acc[i][j] = 0.0f;

    for (int kc = 0; kc < 2; kc++) {
        __syncthreads();   // 1st iter: covers As/b2s fill; later: protect Bs reuse
        for (int t = tid; t < 32 * 128; t += 256) Bs[t] = W2[kc * 32 * 128 + t];
        __syncthreads();
#pragma unroll 2
        for (int kk = 0; kk < 32; kk++) {
            int k = kc * 32 + kk;
            float a[16];
#pragma unroll
            for (int i = 0; i < 16; i++) a[i] = As[k * 129 + ty * 16 + i];
            float4 bv = *(const float4*)&Bs[kk * 128 + tx * 4];
#pragma unroll
            for (int i = 0; i < 16; i++) {
                acc[i][0] = fmaf(a[i], bv.x, acc[i][0]);
                acc[i][1] = fmaf(a[i], bv.y, acc[i][1]);
                acc[i][2] = fmaf(a[i], bv.z, acc[i][2]);
                acc[i][3] = fmaf(a[i], bv.w, acc[i][3]);
            }
        }
    }

    float4 bias = *(const float4*)&b2s[tx * 4];
    float sj[4] = {0, 0, 0, 0}, qj[4] = {0, 0, 0, 0};
#pragma unroll
    for (int i = 0; i < 16; i++) {
        int gr = row0 + ty * 16 + i;
        if (gr < n) {
            float4 o;
            o.x = acc[i][0] + bias.x; o.y = acc[i][1] + bias.y;
            o.z = acc[i][2] + bias.z; o.w = acc[i][3] + bias.w;
            float w = (float)g_count[gr];
            sj[0] += w * o.x; qj[0] += w * o.x * o.x;
            sj[1] += w * o.y; qj[1] += w * o.y * o.y;
            sj[2] += w * o.z; qj[2] += w * o.z * o.z;
            sj[3] += w * o.w; qj[3] += w * o.w * o.w;
            union { uint2 u; __half2 h[2]; } pk;
            pk.h[0] = __floats2half2_rn(o.x, o.y);
            pk.h[1] = __floats2half2_rn(o.z, o.w);
            *(uint2*)&g_T2h[(size_t)gr * COUT + tx * 4] = pk.u;
        }
    }

    // block-level stats reduction (reuse As as scratch: 2 x 8 x 128 floats)
    __syncthreads();
    float* shs = As;
    float* shq = As + 1024;
#pragma unroll
    for (int j = 0; j < 4; j++) {
        shs[ty * 128 + tx * 4 + j] = sj[j];
        shq[ty * 128 + tx * 4 + j] = qj[j];
    }
    __syncthreads();
    if (tid < 128) {
        double s = 0.0, q = 0.0;
#pragma unroll
        for (int u = 0; u < 8; u++) { s += (double)shs[u * 128 + tid]; q += (double)shq[u * 128 + tid]; }
        int slot = blockIdx.x & (NSLOT - 1);
        atomicAdd(&g_sum2[slot * COUT + tid], s);
        atomicAdd(&g_sq2[slot * COUT + tid], q);
    }
}

// ---------------- K6: gather + bn2 affine + relu + max over k (fp16 table) -------
// One warp per output point. Lane l owns channels 4l..4l+3.
__global__ __launch_bounds__(256) void k_gather(const void* __restrict__ idxp,
                                                float* __restrict__ out, int n, int k) {
    int warp = (blockIdx.x * blockDim.x + threadIdx.x) >> 5;
    int lane = threadIdx.x & 31;
    if (warp >= n) return;
    int is64 = g_is64;

    float4 s2 = *(const float4*)&g_s2[lane * 4];
    float4 t2 = *(const float4*)&g_t2[lane * 4];
    float m0 = 0.f, m1 = 0.f, m2 = 0.f, m3 = 0.f;   // relu => result >= 0

    if (k == 16) {
        int r_mine = 0;
        if (lane < 16) {
            if (is64) r_mine = (int)((const long long*)idxp)[(size_t)warp * 16 + lane];
            else      r_mine = ((const int*)idxp)[(size_t)warp * 16 + lane];
        }
#pragma unroll
        for (int j = 0; j < 16; j++) {
            int r = __shfl_sync(0xffffffffu, r_mine, j);
            uint2 v = *(const uint2*)&g_T2h[(size_t)r * COUT + lane * 4];
            float2 f01 = __half22float2(*(__half2*)&v.x);
            float2 f23 = __half22float2(*(__half2*)&v.y);
            m0 = fmaxf(m0, fmaf(s2.x, f01.x, t2.x));
            m1 = fmaxf(m1, fmaf(s2.y, f01.y, t2.y));
            m2 = fmaxf(m2, fmaf(s2.z, f23.x, t2.z));
            m3 = fmaxf(m3, fmaf(s2.w, f23.y, t2.w));
        }
    } else {
        for (int j = 0; j < k; j++) {
            int r;
            if (is64) r = (int)((const long long*)idxp)[(size_t)warp * k + j];
            else      r = ((const int*)idxp)[(size_t)warp * k + j];
            uint2 v = *(const uint2*)&g_T2h[(size_t)r * COUT + lane * 4];
            float2 f01 = __half22float2(*(__half2*)&v.x);
            float2 f23 = __half22float2(*(__half2*)&v.y);
            m0 = fmaxf(m0, fmaf(s2.x, f01.x, t2.x));
            m1 = fmaxf(m1, fmaf(s2.y, f01.y, t2.y));
            m2 = fmaxf(m2, fmaf(s2.z, f23.x, t2.z));
            m3 = fmaxf(m3, fmaf(s2.w, f23.y, t2.w));
        }
    }
    *(float4*)&out[(size_t)warp * COUT + lane * 4] = make_float4(m0, m1, m2, m3);
}

// ---------------- host launcher ----------------
extern "C" void kernel_launch(void* const* d_in, const int* in_sizes, int n_in,
                              void* d_out, int out_size) {
    const float* feat = (const float*)d_in[0];
    const void*  idx  = d_in[1];
    const float* W1   = (const float*)d_in[2];
    const float* b1   = (const float*)d_in[3];
    const float* g1   = (const float*)d_in[4];
    const float* be1  = (const float*)d_in[5];
    const float* W2   = (const float*)d_in[6];
    const float* b2   = (const float*)d_in[7];
    const float* g2   = (const float*)d_in[8];
    const float* be2  = (const float*)d_in[9];
    float* out = (float*)d_out;

    int n  = in_sizes[0] / CIN;      // 100000
    int nk = in_sizes[1];            // n * k
    int k  = nk / n;                 // 16
    double M = (double)nk;

    cudaFuncSetAttribute(k_gemm1, cudaFuncAttributeMaxDynamicSharedMemorySize, SMEM1);
    cudaFuncSetAttribute(k_gemm2, cudaFuncAttributeMaxDynamicSharedMemorySize, SMEM2);

    k_zero<<<(n + 255) / 256, 256>>>(n);
    k_detect<<<1, 64>>>((const int*)idx, nk);
    k_hist<<<512, 256>>>(idx, nk);

    k_gemm1<<<(n + 127) / 128, 256, SMEM1>>>(feat, W1, b1, n);
    k_fin<CMID><<<1, CMID>>>(g1, be1, M);

    k_gemm2<<<(n + 127) / 128, 256, SMEM2>>>(W2, b2, n);
    k_fin<COUT><<<1, COUT>>>(g2, be2, M);

    k_gather<<<(n + 7) / 8, 256>>>(idx, out, n, k);
}